// round 4
// baseline (speedup 1.0000x reference)
#include <cuda_runtime.h>
#include <cuda_bf16.h>
#include <cstdint>
#include <math.h>

#define BB 32
#define CC 1024
#define QQ 128
#define DD 256
#define FF 1024

// ---- scratch: device globals (no allocations allowed) ----
__device__ float g_c2q[BB * CC * DD];            // 33.5 MB
__device__ float g_h[(size_t)BB * CC * FF];      // 134 MB
__device__ float g_m[BB * CC];
__device__ float g_qw[BB * QQ];
__device__ float g_cw[BB * CC];
__device__ float g_q2c[BB * DD];

// ================= K0: qw[b,q] = q.wq ; cw[b,c] = c.wc =================
__global__ void k_dots(const float* __restrict__ q, const float* __restrict__ ctx,
                       const float* __restrict__ wq, const float* __restrict__ wc)
{
    int w = (blockIdx.x * blockDim.x + threadIdx.x) >> 5;
    int lane = threadIdx.x & 31;
    const int NQ = BB * QQ, NC = BB * CC;
    if (w < NQ) {
        const float* v = q + (size_t)w * DD;
        float s = 0.f;
        #pragma unroll
        for (int i = 0; i < DD / 32; i++) s = fmaf(v[lane + i * 32], wq[lane + i * 32], s);
        #pragma unroll
        for (int o = 16; o; o >>= 1) s += __shfl_xor_sync(0xffffffffu, s, o);
        if (!lane) g_qw[w] = s;
    } else if (w < NQ + NC) {
        int ww = w - NQ;
        const float* v = ctx + (size_t)ww * DD;
        float s = 0.f;
        #pragma unroll
        for (int i = 0; i < DD / 32; i++) s = fmaf(v[lane + i * 32], wc[lane + i * 32], s);
        #pragma unroll
        for (int o = 16; o; o >>= 1) s += __shfl_xor_sync(0xffffffffu, s, o);
        if (!lane) g_cw[ww] = s;
    }
}

// ============ K1: fused sim -> softmax -> c2q, saves rowmax (fp32 exact) ============
#define K1_SMEM_BYTES (28032 * 4)
__global__ void __launch_bounds__(256) k_attn(
    const float* __restrict__ ctx, const float* __restrict__ question,
    const float* __restrict__ wm)
{
    extern __shared__ float sm[];
    float* Ps    = sm;
    float* Qs2   = sm + 16896;
    float* red   = sm + 25600;
    float* rowm  = sm + 27776;
    float* rowiv = sm + 27904;
    float* Cs    = Ps;            // phase-1 alias
    float* Qs    = Ps + 4224;

    const int b = blockIdx.y, c0 = blockIdx.x << 7;
    const int tid = threadIdx.x, tx = tid & 15, ty = tid >> 4;
    const float* ctxb = ctx + ((size_t)b * CC + c0) * DD;
    const float* qb   = question + (size_t)b * QQ * DD;

    float acc[8][8];
    #pragma unroll
    for (int i = 0; i < 8; i++)
        #pragma unroll
        for (int j = 0; j < 8; j++) acc[i][j] = 0.f;

    for (int dc = 0; dc < DD; dc += 32) {
        #pragma unroll
        for (int i = 0; i < 4; i++) {
            int idx = tid + (i << 8);
            int row = idx >> 3, kk = (idx & 7) << 2;
            float4 v = *(const float4*)(ctxb + (size_t)row * DD + dc + kk);
            Cs[(kk + 0) * 132 + row] = v.x;
            Cs[(kk + 1) * 132 + row] = v.y;
            Cs[(kk + 2) * 132 + row] = v.z;
            Cs[(kk + 3) * 132 + row] = v.w;
            float4 u  = *(const float4*)(qb + (size_t)row * DD + dc + kk);
            float4 w4 = *(const float4*)(wm + dc + kk);
            Qs[(kk + 0) * 132 + row] = u.x * w4.x;
            Qs[(kk + 1) * 132 + row] = u.y * w4.y;
            Qs[(kk + 2) * 132 + row] = u.z * w4.z;
            Qs[(kk + 3) * 132 + row] = u.w * w4.w;
        }
        __syncthreads();
        #pragma unroll 8
        for (int k = 0; k < 32; k++) {
            float4 a0 = *(const float4*)&Cs[k * 132 + (ty << 3)];
            float4 a1 = *(const float4*)&Cs[k * 132 + (ty << 3) + 4];
            float4 b0 = *(const float4*)&Qs[k * 132 + (tx << 3)];
            float4 b1 = *(const float4*)&Qs[k * 132 + (tx << 3) + 4];
            float ar[8] = {a0.x, a0.y, a0.z, a0.w, a1.x, a1.y, a1.z, a1.w};
            float br[8] = {b0.x, b0.y, b0.z, b0.w, b1.x, b1.y, b1.z, b1.w};
            #pragma unroll
            for (int i = 0; i < 8; i++)
                #pragma unroll
                for (int j = 0; j < 8; j++)
                    acc[i][j] = fmaf(ar[i], br[j], acc[i][j]);
        }
        __syncthreads();
    }

    float cb[8], qbv[8];
    #pragma unroll
    for (int i = 0; i < 8; i++) cb[i] = g_cw[b * CC + c0 + (ty << 3) + i];
    #pragma unroll
    for (int j = 0; j < 8; j++) qbv[j] = g_qw[b * QQ + (tx << 3) + j];
    #pragma unroll
    for (int i = 0; i < 8; i++)
        #pragma unroll
        for (int j = 0; j < 8; j++) acc[i][j] += cb[i] + qbv[j];

    #pragma unroll
    for (int i = 0; i < 8; i++) {
        float m = acc[i][0];
        #pragma unroll
        for (int j = 1; j < 8; j++) m = fmaxf(m, acc[i][j]);
        red[((ty << 3) + i) * 17 + tx] = m;
    }
    __syncthreads();
    if (tid < 128) {
        float m = red[tid * 17];
        #pragma unroll
        for (int t = 1; t < 16; t++) m = fmaxf(m, red[tid * 17 + t]);
        rowm[tid] = m;
        g_m[b * CC + c0 + tid] = m;
    }
    __syncthreads();
    #pragma unroll
    for (int i = 0; i < 8; i++) {
        float rm = rowm[(ty << 3) + i];
        float s = 0.f;
        #pragma unroll
        for (int j = 0; j < 8; j++) { acc[i][j] = expf(acc[i][j] - rm); s += acc[i][j]; }
        red[((ty << 3) + i) * 17 + tx] = s;
    }
    __syncthreads();
    if (tid < 128) {
        float s = 0.f;
        #pragma unroll
        for (int t = 0; t < 16; t++) s += red[tid * 17 + t];
        rowiv[tid] = 1.0f / s;
    }
    __syncthreads();
    #pragma unroll
    for (int i = 0; i < 8; i++) {
        float riv = rowiv[(ty << 3) + i];
        #pragma unroll
        for (int j = 0; j < 8; j++)
            Ps[((tx << 3) + j) * 132 + (ty << 3) + i] = acc[i][j] * riv;
    }
    __syncthreads();

    float* outp = g_c2q + ((size_t)b * CC + c0) * DD;
    for (int db = 0; db < DD; db += 64) {
        #pragma unroll
        for (int i = 0; i < 8; i++) {
            int idx = tid + (i << 8);
            int qrow = idx >> 4, c4 = (idx & 15) << 2;
            *(float4*)&Qs2[qrow * 68 + c4] = *(const float4*)(qb + (size_t)qrow * DD + db + c4);
        }
        __syncthreads();
        float o[8][4];
        #pragma unroll
        for (int i = 0; i < 8; i++)
            #pragma unroll
            for (int j = 0; j < 4; j++) o[i][j] = 0.f;
        #pragma unroll 8
        for (int qk = 0; qk < 128; qk++) {
            float4 p0 = *(const float4*)&Ps[qk * 132 + (ty << 3)];
            float4 p1 = *(const float4*)&Ps[qk * 132 + (ty << 3) + 4];
            float4 qv = *(const float4*)&Qs2[qk * 68 + (tx << 2)];
            float pr[8] = {p0.x, p0.y, p0.z, p0.w, p1.x, p1.y, p1.z, p1.w};
            #pragma unroll
            for (int i = 0; i < 8; i++) {
                o[i][0] = fmaf(pr[i], qv.x, o[i][0]);
                o[i][1] = fmaf(pr[i], qv.y, o[i][1]);
                o[i][2] = fmaf(pr[i], qv.z, o[i][2]);
                o[i][3] = fmaf(pr[i], qv.w, o[i][3]);
            }
        }
        #pragma unroll
        for (int i = 0; i < 8; i++)
            *(float4*)&outp[(size_t)((ty << 3) + i) * DD + db + (tx << 2)] =
                make_float4(o[i][0], o[i][1], o[i][2], o[i][3]);
        __syncthreads();
    }
}

// ============ K2: q2c[b,d] = softmax_c(rowmax) . context ============
__global__ void k_q2c(const float* __restrict__ ctx)
{
    __shared__ float w[CC];
    __shared__ float red[256];
    const int b = blockIdx.x, tid = threadIdx.x;
    float lm = -1e30f;
    for (int c = tid; c < CC; c += 256) { float v = g_m[b * CC + c]; w[c] = v; lm = fmaxf(lm, v); }
    red[tid] = lm; __syncthreads();
    for (int s = 128; s > 0; s >>= 1) { if (tid < s) red[tid] = fmaxf(red[tid], red[tid + s]); __syncthreads(); }
    float mx = red[0]; __syncthreads();
    float ls = 0.f;
    for (int c = tid; c < CC; c += 256) { float e = expf(w[c] - mx); w[c] = e; ls += e; }
    red[tid] = ls; __syncthreads();
    for (int s = 128; s > 0; s >>= 1) { if (tid < s) red[tid] += red[tid + s]; __syncthreads(); }
    float inv = 1.0f / red[0]; __syncthreads();
    float accv = 0.f;
    const float* cb = ctx + (size_t)b * CC * DD + tid;   // tid == d
    for (int c = 0; c < CC; c++) accv = fmaf(w[c], cb[(size_t)c * DD], accv);
    g_q2c[b * DD + tid] = accv * inv;
}

// ============ GEMM: bf16x3 split tensor-core, 128x128 tile ============
// MODE 0: A = att (built on the fly from ctx/g_c2q/g_q2c), writes g_h = A@W1^T+b1, masked
// MODE 1: A = g_h, writes out = relu((A@W2^T + b2) * mask)
#define SROW 40

__device__ __forceinline__ void split2(float x, float y, uint32_t& hi, uint32_t& lo) {
    __nv_bfloat16 hx = __float2bfloat16(x), hy = __float2bfloat16(y);
    __nv_bfloat16 lx = __float2bfloat16(x - __bfloat162float(hx));
    __nv_bfloat16 ly = __float2bfloat16(y - __bfloat162float(hy));
    __nv_bfloat162 H; H.x = hx; H.y = hy;
    __nv_bfloat162 L; L.x = lx; L.y = ly;
    hi = *reinterpret_cast<uint32_t*>(&H);
    lo = *reinterpret_cast<uint32_t*>(&L);
}

__device__ __forceinline__ void mma_bf16(float* c, const uint32_t* a, uint32_t b0, uint32_t b1) {
    asm volatile(
        "mma.sync.aligned.m16n8k16.row.col.f32.bf16.bf16.f32 "
        "{%0,%1,%2,%3},{%4,%5,%6,%7},{%8,%9},{%0,%1,%2,%3};"
        : "+f"(c[0]), "+f"(c[1]), "+f"(c[2]), "+f"(c[3])
        : "r"(a[0]), "r"(a[1]), "r"(a[2]), "r"(a[3]), "r"(b0), "r"(b1));
}

template <int MODE>
__global__ void __launch_bounds__(256) k_gemm(
    const float* __restrict__ ctx,
    const float* __restrict__ W, const float* __restrict__ bias,
    const int* __restrict__ mask, float* __restrict__ out)
{
    __shared__ uint16_t Ah[128 * SROW], Al[128 * SROW];
    __shared__ uint16_t Bh[128 * SROW], Bl[128 * SROW];
    const int tid = threadIdx.x, lane = tid & 31, wrp = tid >> 5;
    const int g = lane >> 2, t4 = lane & 3;
    const int wm0 = (wrp >> 1) * 32, wn0 = (wrp & 1) * 64;
    const int bm = blockIdx.x, bn = blockIdx.y;
    const int bb = (bm << 7) >> 10;

    float acc[2][8][4];
    #pragma unroll
    for (int i = 0; i < 2; i++)
        #pragma unroll
        for (int j = 0; j < 8; j++)
            #pragma unroll
            for (int l = 0; l < 4; l++) acc[i][j][l] = 0.f;

    for (int kt = 0; kt < FF / 32; kt++) {
        const int k0 = kt * 32;
        #pragma unroll
        for (int i = 0; i < 4; i++) {
            int idx = tid + (i << 8);
            int row = idx >> 3, kk = (idx & 7) << 2;
            float4 bv = *(const float4*)(W + (size_t)((bn << 7) + row) * FF + k0 + kk);
            uint32_t h0, l0, h1, l1;
            split2(bv.x, bv.y, h0, l0);
            split2(bv.z, bv.w, h1, l1);
            *(uint32_t*)&Bh[row * SROW + kk] = h0;
            *(uint32_t*)&Bh[row * SROW + kk + 2] = h1;
            *(uint32_t*)&Bl[row * SROW + kk] = l0;
            *(uint32_t*)&Bl[row * SROW + kk + 2] = l1;

            float4 av;
            if (MODE == 1) {
                av = *(const float4*)(g_h + (size_t)((bm << 7) + row) * FF + k0 + kk);
            } else {
                const int seg = k0 >> 8;
                const int kd  = (k0 & 255) + kk;
                const size_t base = (size_t)((bm << 7) + row) * DD + kd;
                if (seg == 0) {
                    av = *(const float4*)(ctx + base);
                } else if (seg == 1) {
                    av = *(const float4*)(g_c2q + base);
                } else if (seg == 2) {
                    float4 cv = *(const float4*)(ctx + base);
                    float4 qv = *(const float4*)(g_c2q + base);
                    av = make_float4(cv.x * qv.x, cv.y * qv.y, cv.z * qv.z, cv.w * qv.w);
                } else {
                    float4 cv = *(const float4*)(ctx + base);
                    float4 qv = *(const float4*)(g_q2c + bb * DD + kd);
                    av = make_float4(cv.x * qv.x, cv.y * qv.y, cv.z * qv.z, cv.w * qv.w);
                }
            }
            split2(av.x, av.y, h0, l0);
            split2(av.z, av.w, h1, l1);
            *(uint32_t*)&Ah[row * SROW + kk] = h0;
            *(uint32_t*)&Ah[row * SROW + kk + 2] = h1;
            *(uint32_t*)&Al[row * SROW + kk] = l0;
            *(uint32_t*)&Al[row * SROW + kk + 2] = l1;
        }
        __syncthreads();

        #pragma unroll
        for (int ks = 0; ks < 32; ks += 16) {
            uint32_t ah[2][4], al[2][4];
            #pragma unroll
            for (int mt = 0; mt < 2; mt++) {
                int base = (wm0 + mt * 16 + g) * SROW + ks + 2 * t4;
                ah[mt][0] = *(const uint32_t*)&Ah[base];
                ah[mt][1] = *(const uint32_t*)&Ah[base + 8 * SROW];
                ah[mt][2] = *(const uint32_t*)&Ah[base + 8];
                ah[mt][3] = *(const uint32_t*)&Ah[base + 8 * SROW + 8];
                al[mt][0] = *(const uint32_t*)&Al[base];
                al[mt][1] = *(const uint32_t*)&Al[base + 8 * SROW];
                al[mt][2] = *(const uint32_t*)&Al[base + 8];
                al[mt][3] = *(const uint32_t*)&Al[base + 8 * SROW + 8];
            }
            #pragma unroll
            for (int nf = 0; nf < 8; nf++) {
                int nb = (wn0 + nf * 8 + g) * SROW + ks + 2 * t4;
                uint32_t bh0 = *(const uint32_t*)&Bh[nb];
                uint32_t bh1 = *(const uint32_t*)&Bh[nb + 8];
                uint32_t bl0 = *(const uint32_t*)&Bl[nb];
                uint32_t bl1 = *(const uint32_t*)&Bl[nb + 8];
                #pragma unroll
                for (int mt = 0; mt < 2; mt++) {
                    mma_bf16(acc[mt][nf], ah[mt], bh0, bh1);
                    mma_bf16(acc[mt][nf], ah[mt], bl0, bl1);
                    mma_bf16(acc[mt][nf], al[mt], bh0, bh1);
                }
            }
        }
        __syncthreads();
    }

    // epilogue: +bias, mask (int32!), (relu), store
    float* op = (MODE == 0) ? g_h : out;
    #pragma unroll
    for (int mt = 0; mt < 2; mt++) {
        int r0 = (bm << 7) + wm0 + mt * 16 + g;
        float mv0 = mask[bb * CC + (r0 & 1023)] ? 1.f : 0.f;
        float mv1 = mask[bb * CC + ((r0 + 8) & 1023)] ? 1.f : 0.f;
        #pragma unroll
        for (int nf = 0; nf < 8; nf++) {
            int col = (bn << 7) + wn0 + nf * 8 + 2 * t4;
            float bz0 = bias[col], bz1 = bias[col + 1];
            float2 v0, v1;
            v0.x = (acc[mt][nf][0] + bz0) * mv0;
            v0.y = (acc[mt][nf][1] + bz1) * mv0;
            v1.x = (acc[mt][nf][2] + bz0) * mv1;
            v1.y = (acc[mt][nf][3] + bz1) * mv1;
            if (MODE == 1) {
                v0.x = fmaxf(v0.x, 0.f); v0.y = fmaxf(v0.y, 0.f);
                v1.x = fmaxf(v1.x, 0.f); v1.y = fmaxf(v1.y, 0.f);
            }
            *(float2*)&op[(size_t)r0 * FF + col] = v0;
            *(float2*)&op[(size_t)(r0 + 8) * FF + col] = v1;
        }
    }
}

// =========================== launch ===========================
extern "C" void kernel_launch(void* const* d_in, const int* in_sizes, int n_in,
                              void* d_out, int out_size)
{
    const float* ctx = (const float*)d_in[0];
    const float* qst = (const float*)d_in[1];
    const int*   mask = (const int*)d_in[2];     // bool promoted to int32 by harness
    const float* wq = (const float*)d_in[3];
    const float* wc = (const float*)d_in[4];
    const float* wm = (const float*)d_in[5];
    const float* W1 = (const float*)d_in[6];
    const float* b1 = (const float*)d_in[7];
    const float* W2 = (const float*)d_in[8];
    const float* b2 = (const float*)d_in[9];
    float* out = (float*)d_out;

    cudaFuncSetAttribute(k_attn, cudaFuncAttributeMaxDynamicSharedMemorySize, K1_SMEM_BYTES);

    int nwarps = BB * QQ + BB * CC;
    k_dots<<<(nwarps + 7) / 8, 256>>>(qst, ctx, wq, wc);

    k_attn<<<dim3(CC / 128, BB), 256, K1_SMEM_BYTES>>>(ctx, qst, wm);

    k_q2c<<<BB, 256>>>(ctx);

    k_gemm<0><<<dim3(BB * CC / 128, FF / 128), 256>>>(ctx, W1, b1, mask, nullptr);
    k_gemm<1><<<dim3(BB * CC / 128, FF / 128), 256>>>(ctx, W2, b2, mask, out);
}

// round 5
// speedup vs baseline: 1.8284x; 1.8284x over previous
#include <cuda_runtime.h>
#include <cuda_bf16.h>
#include <cstdint>
#include <math.h>

#define BB 32
#define CC 1024
#define QQ 128
#define DD 256
#define FF 1024
#define MM (BB * CC)   // 32768 rows

// ---- scratch: device globals (no allocations allowed) ----
__device__ float g_c2q[BB * CC * DD];                    // 33.5 MB
__device__ float g_m[BB * CC];
__device__ float g_qw[BB * QQ];
__device__ float g_cw[BB * CC];
__device__ float g_q2c[BB * DD];
// split bf16 operands
__device__ __nv_bfloat16 g_ah[(size_t)MM * FF];          // att hi (64 MB)
__device__ __nv_bfloat16 g_al[(size_t)MM * FF];          // att lo
__device__ __nv_bfloat16 g_hh[(size_t)MM * FF];          // h hi
__device__ __nv_bfloat16 g_hl[(size_t)MM * FF];          // h lo
__device__ __nv_bfloat16 g_w1h[FF * FF], g_w1l[FF * FF];
__device__ __nv_bfloat16 g_w2h[FF * FF], g_w2l[FF * FF];

__device__ __forceinline__ void bsplit(float x, __nv_bfloat16& h, __nv_bfloat16& l) {
    h = __float2bfloat16(x);
    l = __float2bfloat16(x - __bfloat162float(h));
}

#define CP16(smem_b, gptr) \
    asm volatile("cp.async.cg.shared.global [%0], [%1], 16;" :: "r"(smem_b), "l"(gptr))

// ================= K0: qw[b,q]=q.wq ; cw[b,c]=c.wc =================
__global__ void k_dots(const float* __restrict__ q, const float* __restrict__ ctx,
                       const float* __restrict__ wq, const float* __restrict__ wc)
{
    int w = (blockIdx.x * blockDim.x + threadIdx.x) >> 5;
    int lane = threadIdx.x & 31;
    const int NQ = BB * QQ, NC = BB * CC;
    if (w < NQ) {
        const float* v = q + (size_t)w * DD;
        float s = 0.f;
        #pragma unroll
        for (int i = 0; i < DD / 32; i++) s = fmaf(v[lane + i * 32], wq[lane + i * 32], s);
        #pragma unroll
        for (int o = 16; o; o >>= 1) s += __shfl_xor_sync(0xffffffffu, s, o);
        if (!lane) g_qw[w] = s;
    } else if (w < NQ + NC) {
        int ww = w - NQ;
        const float* v = ctx + (size_t)ww * DD;
        float s = 0.f;
        #pragma unroll
        for (int i = 0; i < DD / 32; i++) s = fmaf(v[lane + i * 32], wc[lane + i * 32], s);
        #pragma unroll
        for (int o = 16; o; o >>= 1) s += __shfl_xor_sync(0xffffffffu, s, o);
        if (!lane) g_cw[ww] = s;
    }
}

// ============ K1: fused sim -> softmax -> c2q (exact fp32) ============
#define K1_SMEM_BYTES (28032 * 4)
__global__ void __launch_bounds__(256) k_attn(
    const float* __restrict__ ctx, const float* __restrict__ question,
    const float* __restrict__ wm)
{
    extern __shared__ float sm[];
    float* Ps    = sm;
    float* Qs2   = sm + 16896;
    float* red   = sm + 25600;
    float* rowm  = sm + 27776;
    float* rowiv = sm + 27904;
    float* Cs    = Ps;
    float* Qs    = Ps + 4224;

    const int b = blockIdx.y, c0 = blockIdx.x << 7;
    const int tid = threadIdx.x, tx = tid & 15, ty = tid >> 4;
    const float* ctxb = ctx + ((size_t)b * CC + c0) * DD;
    const float* qb   = question + (size_t)b * QQ * DD;

    float acc[8][8];
    #pragma unroll
    for (int i = 0; i < 8; i++)
        #pragma unroll
        for (int j = 0; j < 8; j++) acc[i][j] = 0.f;

    for (int dc = 0; dc < DD; dc += 32) {
        #pragma unroll
        for (int i = 0; i < 4; i++) {
            int idx = tid + (i << 8);
            int row = idx >> 3, kk = (idx & 7) << 2;
            float4 v = *(const float4*)(ctxb + (size_t)row * DD + dc + kk);
            Cs[(kk + 0) * 132 + row] = v.x;
            Cs[(kk + 1) * 132 + row] = v.y;
            Cs[(kk + 2) * 132 + row] = v.z;
            Cs[(kk + 3) * 132 + row] = v.w;
            float4 u  = *(const float4*)(qb + (size_t)row * DD + dc + kk);
            float4 w4 = *(const float4*)(wm + dc + kk);
            Qs[(kk + 0) * 132 + row] = u.x * w4.x;
            Qs[(kk + 1) * 132 + row] = u.y * w4.y;
            Qs[(kk + 2) * 132 + row] = u.z * w4.z;
            Qs[(kk + 3) * 132 + row] = u.w * w4.w;
        }
        __syncthreads();
        #pragma unroll 8
        for (int k = 0; k < 32; k++) {
            float4 a0 = *(const float4*)&Cs[k * 132 + (ty << 3)];
            float4 a1 = *(const float4*)&Cs[k * 132 + (ty << 3) + 4];
            float4 b0 = *(const float4*)&Qs[k * 132 + (tx << 3)];
            float4 b1 = *(const float4*)&Qs[k * 132 + (tx << 3) + 4];
            float ar[8] = {a0.x, a0.y, a0.z, a0.w, a1.x, a1.y, a1.z, a1.w};
            float br[8] = {b0.x, b0.y, b0.z, b0.w, b1.x, b1.y, b1.z, b1.w};
            #pragma unroll
            for (int i = 0; i < 8; i++)
                #pragma unroll
                for (int j = 0; j < 8; j++)
                    acc[i][j] = fmaf(ar[i], br[j], acc[i][j]);
        }
        __syncthreads();
    }

    float cb[8], qbv[8];
    #pragma unroll
    for (int i = 0; i < 8; i++) cb[i] = g_cw[b * CC + c0 + (ty << 3) + i];
    #pragma unroll
    for (int j = 0; j < 8; j++) qbv[j] = g_qw[b * QQ + (tx << 3) + j];
    #pragma unroll
    for (int i = 0; i < 8; i++)
        #pragma unroll
        for (int j = 0; j < 8; j++) acc[i][j] += cb[i] + qbv[j];

    #pragma unroll
    for (int i = 0; i < 8; i++) {
        float m = acc[i][0];
        #pragma unroll
        for (int j = 1; j < 8; j++) m = fmaxf(m, acc[i][j]);
        red[((ty << 3) + i) * 17 + tx] = m;
    }
    __syncthreads();
    if (tid < 128) {
        float m = red[tid * 17];
        #pragma unroll
        for (int t = 1; t < 16; t++) m = fmaxf(m, red[tid * 17 + t]);
        rowm[tid] = m;
        g_m[b * CC + c0 + tid] = m;
    }
    __syncthreads();
    #pragma unroll
    for (int i = 0; i < 8; i++) {
        float rm = rowm[(ty << 3) + i];
        float s = 0.f;
        #pragma unroll
        for (int j = 0; j < 8; j++) { acc[i][j] = expf(acc[i][j] - rm); s += acc[i][j]; }
        red[((ty << 3) + i) * 17 + tx] = s;
    }
    __syncthreads();
    if (tid < 128) {
        float s = 0.f;
        #pragma unroll
        for (int t = 0; t < 16; t++) s += red[tid * 17 + t];
        rowiv[tid] = 1.0f / s;
    }
    __syncthreads();
    #pragma unroll
    for (int i = 0; i < 8; i++) {
        float riv = rowiv[(ty << 3) + i];
        #pragma unroll
        for (int j = 0; j < 8; j++)
            Ps[((tx << 3) + j) * 132 + (ty << 3) + i] = acc[i][j] * riv;
    }
    __syncthreads();

    float* outp = g_c2q + ((size_t)b * CC + c0) * DD;
    for (int db = 0; db < DD; db += 64) {
        #pragma unroll
        for (int i = 0; i < 8; i++) {
            int idx = tid + (i << 8);
            int qrow = idx >> 4, c4 = (idx & 15) << 2;
            *(float4*)&Qs2[qrow * 68 + c4] = *(const float4*)(qb + (size_t)qrow * DD + db + c4);
        }
        __syncthreads();
        float o[8][4];
        #pragma unroll
        for (int i = 0; i < 8; i++)
            #pragma unroll
            for (int j = 0; j < 4; j++) o[i][j] = 0.f;
        #pragma unroll 8
        for (int qk = 0; qk < 128; qk++) {
            float4 p0 = *(const float4*)&Ps[qk * 132 + (ty << 3)];
            float4 p1 = *(const float4*)&Ps[qk * 132 + (ty << 3) + 4];
            float4 qv = *(const float4*)&Qs2[qk * 68 + (tx << 2)];
            float pr[8] = {p0.x, p0.y, p0.z, p0.w, p1.x, p1.y, p1.z, p1.w};
            #pragma unroll
            for (int i = 0; i < 8; i++) {
                o[i][0] = fmaf(pr[i], qv.x, o[i][0]);
                o[i][1] = fmaf(pr[i], qv.y, o[i][1]);
                o[i][2] = fmaf(pr[i], qv.z, o[i][2]);
                o[i][3] = fmaf(pr[i], qv.w, o[i][3]);
            }
        }
        #pragma unroll
        for (int i = 0; i < 8; i++)
            *(float4*)&outp[(size_t)((ty << 3) + i) * DD + db + (tx << 2)] =
                make_float4(o[i][0], o[i][1], o[i][2], o[i][3]);
        __syncthreads();
    }
}

// ============ K2: q2c[b,d] = softmax_c(rowmax) . context ============
__global__ void k_q2c(const float* __restrict__ ctx)
{
    __shared__ float w[CC];
    __shared__ float red[256];
    const int b = blockIdx.x, tid = threadIdx.x;
    float lm = -1e30f;
    for (int c = tid; c < CC; c += 256) { float v = g_m[b * CC + c]; w[c] = v; lm = fmaxf(lm, v); }
    red[tid] = lm; __syncthreads();
    for (int s = 128; s > 0; s >>= 1) { if (tid < s) red[tid] = fmaxf(red[tid], red[tid + s]); __syncthreads(); }
    float mx = red[0]; __syncthreads();
    float ls = 0.f;
    for (int c = tid; c < CC; c += 256) { float e = expf(w[c] - mx); w[c] = e; ls += e; }
    red[tid] = ls; __syncthreads();
    for (int s = 128; s > 0; s >>= 1) { if (tid < s) red[tid] += red[tid + s]; __syncthreads(); }
    float inv = 1.0f / red[0]; __syncthreads();
    float accv = 0.f;
    const float* cb = ctx + (size_t)b * CC * DD + tid;
    for (int c = 0; c < CC; c++) accv = fmaf(w[c], cb[(size_t)c * DD], accv);
    g_q2c[b * DD + tid] = accv * inv;
}

// ============ prep: split W into bf16 hi/lo ============
__global__ void k_splitw(const float* __restrict__ W,
                         __nv_bfloat16* __restrict__ H, __nv_bfloat16* __restrict__ L)
{
    int t = blockIdx.x * 256 + threadIdx.x;      // one float4 per thread
    float4 v = *(const float4*)(W + (size_t)t * 4);
    __nv_bfloat16 h[4], l[4];
    bsplit(v.x, h[0], l[0]); bsplit(v.y, h[1], l[1]);
    bsplit(v.z, h[2], l[2]); bsplit(v.w, h[3], l[3]);
    *(uint64_t*)(H + (size_t)t * 4) = *(uint64_t*)h;
    *(uint64_t*)(L + (size_t)t * 4) = *(uint64_t*)l;
}

// ============ prep: materialize att in split bf16 ============
__global__ void k_build_att(const float* __restrict__ ctx)
{
    int t = blockIdx.x * 256 + threadIdx.x;      // one float4 of att per thread
    int r  = t >> 8;                              // row 0..MM-1
    int c4 = (t & 255) << 2;                      // col 0..1020
    int seg = c4 >> 8, kd = c4 & 255;
    int bb = r >> 10;
    size_t base = (size_t)r * DD + kd;
    float4 av;
    if (seg == 0) {
        av = *(const float4*)(ctx + base);
    } else if (seg == 1) {
        av = *(const float4*)(g_c2q + base);
    } else if (seg == 2) {
        float4 cv = *(const float4*)(ctx + base);
        float4 qv = *(const float4*)(g_c2q + base);
        av = make_float4(cv.x * qv.x, cv.y * qv.y, cv.z * qv.z, cv.w * qv.w);
    } else {
        float4 cv = *(const float4*)(ctx + base);
        float4 qv = *(const float4*)(g_q2c + bb * DD + kd);
        av = make_float4(cv.x * qv.x, cv.y * qv.y, cv.z * qv.z, cv.w * qv.w);
    }
    __nv_bfloat16 h[4], l[4];
    bsplit(av.x, h[0], l[0]); bsplit(av.y, h[1], l[1]);
    bsplit(av.z, h[2], l[2]); bsplit(av.w, h[3], l[3]);
    size_t o = (size_t)r * FF + c4;
    *(uint64_t*)(g_ah + o) = *(uint64_t*)h;
    *(uint64_t*)(g_al + o) = *(uint64_t*)l;
}

// ============ GEMM: bf16x3, cp.async double-buffered, 128x128 tile ============
// MODE 0: A=g_ah/g_al, writes h as bf16 hi/lo (bias+mask)
// MODE 1: A=g_hh/g_hl, writes fp32 out = relu((.+b2)*mask)
// dyn smem: 2 stages x [Ah|Al|Bh|Bl] each 128x40 bf16 (10240B) = 81920B
#define GEMM_SMEM 81920

__device__ __forceinline__ void mma_bf16(float* c, const uint32_t* a, uint32_t b0, uint32_t b1) {
    asm volatile(
        "mma.sync.aligned.m16n8k16.row.col.f32.bf16.bf16.f32 "
        "{%0,%1,%2,%3},{%4,%5,%6,%7},{%8,%9},{%0,%1,%2,%3};"
        : "+f"(c[0]), "+f"(c[1]), "+f"(c[2]), "+f"(c[3])
        : "r"(a[0]), "r"(a[1]), "r"(a[2]), "r"(a[3]), "r"(b0), "r"(b1));
}

template <int MODE>
__global__ void __launch_bounds__(256, 2) k_gemm(
    const __nv_bfloat16* __restrict__ Ah_g, const __nv_bfloat16* __restrict__ Al_g,
    const __nv_bfloat16* __restrict__ Bh_g, const __nv_bfloat16* __restrict__ Bl_g,
    const float* __restrict__ bias, const int* __restrict__ mask,
    float* __restrict__ out)
{
    extern __shared__ uint16_t sm16[];
    const int tid = threadIdx.x, lane = tid & 31, wrp = tid >> 5;
    const int g = lane >> 2, t4 = lane & 3;
    const int wm0 = (wrp >> 1) * 32, wn0 = (wrp & 1) * 64;
    const int m0 = blockIdx.x << 7, n0 = blockIdx.y << 7;
    const int bb = m0 >> 10;

    float acc[2][8][4];
    #pragma unroll
    for (int i = 0; i < 2; i++)
        #pragma unroll
        for (int j = 0; j < 8; j++)
            #pragma unroll
            for (int l = 0; l < 4; l++) acc[i][j][l] = 0.f;

    const uint32_t sbase = (uint32_t)__cvta_generic_to_shared(sm16);

    // issue one stage of cp.asyncs
    auto load_stage = [&](int s, int kt) {
        const int k0 = kt << 5;
        const uint32_t sb = sbase + s * 40960;
        #pragma unroll
        for (int half = 0; half < 2; half++) {
            int c = tid + (half << 8);            // 0..511
            int row = c >> 2, q = c & 3;
            uint32_t soff = (uint32_t)(row * 40 + q * 8) * 2;
            size_t ga = (size_t)(m0 + row) * FF + k0 + q * 8;
            size_t gb = (size_t)(n0 + row) * FF + k0 + q * 8;
            CP16(sb + soff,          Ah_g + ga);
            CP16(sb + 10240 + soff,  Al_g + ga);
            CP16(sb + 20480 + soff,  Bh_g + gb);
            CP16(sb + 30720 + soff,  Bl_g + gb);
        }
        asm volatile("cp.async.commit_group;");
    };

    load_stage(0, 0);

    for (int kt = 0; kt < FF / 32; kt++) {
        const int cur = kt & 1;
        if (kt + 1 < FF / 32) {
            load_stage(cur ^ 1, kt + 1);
            asm volatile("cp.async.wait_group 1;");
        } else {
            asm volatile("cp.async.wait_group 0;");
        }
        __syncthreads();

        const uint16_t* Ah = sm16 + cur * 20480;
        const uint16_t* Al = Ah + 5120;
        const uint16_t* Bh = Ah + 10240;
        const uint16_t* Bl = Ah + 15360;

        #pragma unroll
        for (int ks = 0; ks < 32; ks += 16) {
            uint32_t ah[2][4], al[2][4];
            #pragma unroll
            for (int mt = 0; mt < 2; mt++) {
                int fb = (wm0 + mt * 16 + g) * 40 + ks + 2 * t4;
                ah[mt][0] = *(const uint32_t*)&Ah[fb];
                ah[mt][1] = *(const uint32_t*)&Ah[fb + 8 * 40];
                ah[mt][2] = *(const uint32_t*)&Ah[fb + 8];
                ah[mt][3] = *(const uint32_t*)&Ah[fb + 8 * 40 + 8];
                al[mt][0] = *(const uint32_t*)&Al[fb];
                al[mt][1] = *(const uint32_t*)&Al[fb + 8 * 40];
                al[mt][2] = *(const uint32_t*)&Al[fb + 8];
                al[mt][3] = *(const uint32_t*)&Al[fb + 8 * 40 + 8];
            }
            #pragma unroll
            for (int nf = 0; nf < 8; nf++) {
                int nb = (wn0 + nf * 8 + g) * 40 + ks + 2 * t4;
                uint32_t bh0 = *(const uint32_t*)&Bh[nb];
                uint32_t bh1 = *(const uint32_t*)&Bh[nb + 8];
                uint32_t bl0 = *(const uint32_t*)&Bl[nb];
                uint32_t bl1 = *(const uint32_t*)&Bl[nb + 8];
                #pragma unroll
                for (int mt = 0; mt < 2; mt++) {
                    mma_bf16(acc[mt][nf], ah[mt], bh0, bh1);
                    mma_bf16(acc[mt][nf], ah[mt], bl0, bl1);
                    mma_bf16(acc[mt][nf], al[mt], bh0, bh1);
                }
            }
        }
        __syncthreads();
    }

    // epilogue
    #pragma unroll
    for (int mt = 0; mt < 2; mt++) {
        int r0 = m0 + wm0 + mt * 16 + g;
        float mv0 = mask[bb * CC + (r0 & 1023)] ? 1.f : 0.f;
        float mv1 = mask[bb * CC + ((r0 + 8) & 1023)] ? 1.f : 0.f;
        #pragma unroll
        for (int nf = 0; nf < 8; nf++) {
            int col = n0 + wn0 + nf * 8 + 2 * t4;
            float bz0 = bias[col], bz1 = bias[col + 1];
            float v00 = (acc[mt][nf][0] + bz0) * mv0;
            float v01 = (acc[mt][nf][1] + bz1) * mv0;
            float v10 = (acc[mt][nf][2] + bz0) * mv1;
            float v11 = (acc[mt][nf][3] + bz1) * mv1;
            if (MODE == 0) {
                __nv_bfloat16 h0, l0, h1, l1;
                size_t o0 = (size_t)r0 * FF + col;
                size_t o1 = (size_t)(r0 + 8) * FF + col;
                bsplit(v00, h0, l0); bsplit(v01, h1, l1);
                *(uint32_t*)(g_hh + o0) = (uint32_t)*(uint16_t*)&h0 | ((uint32_t)*(uint16_t*)&h1 << 16);
                *(uint32_t*)(g_hl + o0) = (uint32_t)*(uint16_t*)&l0 | ((uint32_t)*(uint16_t*)&l1 << 16);
                bsplit(v10, h0, l0); bsplit(v11, h1, l1);
                *(uint32_t*)(g_hh + o1) = (uint32_t)*(uint16_t*)&h0 | ((uint32_t)*(uint16_t*)&h1 << 16);
                *(uint32_t*)(g_hl + o1) = (uint32_t)*(uint16_t*)&l0 | ((uint32_t)*(uint16_t*)&l1 << 16);
            } else {
                float2 a = make_float2(fmaxf(v00, 0.f), fmaxf(v01, 0.f));
                float2 b = make_float2(fmaxf(v10, 0.f), fmaxf(v11, 0.f));
                *(float2*)&out[(size_t)r0 * FF + col] = a;
                *(float2*)&out[(size_t)(r0 + 8) * FF + col] = b;
            }
        }
    }
}

// =========================== launch ===========================
extern "C" void kernel_launch(void* const* d_in, const int* in_sizes, int n_in,
                              void* d_out, int out_size)
{
    const float* ctx = (const float*)d_in[0];
    const float* qst = (const float*)d_in[1];
    const int*   mask = (const int*)d_in[2];     // bool promoted to int32
    const float* wq = (const float*)d_in[3];
    const float* wc = (const float*)d_in[4];
    const float* wm = (const float*)d_in[5];
    const float* W1 = (const float*)d_in[6];
    const float* b1 = (const float*)d_in[7];
    const float* W2 = (const float*)d_in[8];
    const float* b2 = (const float*)d_in[9];
    float* out = (float*)d_out;

    __nv_bfloat16 *w1h, *w1l, *w2h, *w2l, *ah, *al, *hh, *hl;
    cudaGetSymbolAddress((void**)&w1h, g_w1h);
    cudaGetSymbolAddress((void**)&w1l, g_w1l);
    cudaGetSymbolAddress((void**)&w2h, g_w2h);
    cudaGetSymbolAddress((void**)&w2l, g_w2l);
    cudaGetSymbolAddress((void**)&ah,  g_ah);
    cudaGetSymbolAddress((void**)&al,  g_al);
    cudaGetSymbolAddress((void**)&hh,  g_hh);
    cudaGetSymbolAddress((void**)&hl,  g_hl);

    cudaFuncSetAttribute(k_attn, cudaFuncAttributeMaxDynamicSharedMemorySize, K1_SMEM_BYTES);
    cudaFuncSetAttribute(k_gemm<0>, cudaFuncAttributeMaxDynamicSharedMemorySize, GEMM_SMEM);
    cudaFuncSetAttribute(k_gemm<1>, cudaFuncAttributeMaxDynamicSharedMemorySize, GEMM_SMEM);

    // prep: split weights (independent of data path)
    k_splitw<<<FF * FF / 4 / 256, 256>>>(W1, w1h, w1l);
    k_splitw<<<FF * FF / 4 / 256, 256>>>(W2, w2h, w2l);

    int nwarps = BB * QQ + BB * CC;
    k_dots<<<(nwarps + 7) / 8, 256>>>(qst, ctx, wq, wc);
    k_attn<<<dim3(CC / 128, BB), 256, K1_SMEM_BYTES>>>(ctx, qst, wm);
    k_q2c<<<BB, 256>>>(ctx);
    k_build_att<<<MM * 256 / 256, 256>>>(ctx);

    k_gemm<0><<<dim3(MM / 128, FF / 128), 256, GEMM_SMEM>>>(ah, al, w1h, w1l, b1, mask, nullptr);
    k_gemm<1><<<dim3(MM / 128, FF / 128), 256, GEMM_SMEM>>>(hh, hl, w2h, w2l, b2, mask, out);
}

// round 10
// speedup vs baseline: 2.4394x; 1.3341x over previous
#include <cuda_runtime.h>
#include <cuda_fp16.h>
#include <cstdint>
#include <math.h>

#define BB 32
#define CC 1024
#define QQ 128
#define DD 256
#define FF 1024
#define MM (BB * CC)

// ---- scratch: device globals (no allocations allowed) ----
__device__ float g_c2q[BB * CC * DD];
__device__ float g_m[BB * CC];
__device__ float g_qw[BB * QQ];
__device__ float g_cw[BB * CC];
__device__ float g_q2c[BB * DD];
__device__ __half g_a16[(size_t)MM * FF];     // att, fp16 (64 MB)
__device__ __half g_h16[(size_t)MM * FF];     // h,   fp16 (64 MB)
__device__ __half g_w1h[FF * FF], g_w1l[FF * FF];
__device__ __half g_w2h[FF * FF], g_w2l[FF * FF];

__device__ __forceinline__ void hsplit(float x, __half& h, __half& l) {
    h = __float2half_rn(x);
    l = __float2half_rn(x - __half2float(h));
}

#define CP16(smem_b, gptr) \
    asm volatile("cp.async.cg.shared.global [%0], [%1], 16;" :: "r"(smem_b), "l"(gptr))

// ================= K0: qw[b,q]=q.wq ; cw[b,c]=c.wc =================
__global__ void k_dots(const float* __restrict__ q, const float* __restrict__ ctx,
                       const float* __restrict__ wq, const float* __restrict__ wc)
{
    int w = (blockIdx.x * blockDim.x + threadIdx.x) >> 5;
    int lane = threadIdx.x & 31;
    const int NQ = BB * QQ, NC = BB * CC;
    if (w < NQ) {
        const float* v = q + (size_t)w * DD;
        float s = 0.f;
        #pragma unroll
        for (int i = 0; i < DD / 32; i++) s = fmaf(v[lane + i * 32], wq[lane + i * 32], s);
        #pragma unroll
        for (int o = 16; o; o >>= 1) s += __shfl_xor_sync(0xffffffffu, s, o);
        if (!lane) g_qw[w] = s;
    } else if (w < NQ + NC) {
        int ww = w - NQ;
        const float* v = ctx + (size_t)ww * DD;
        float s = 0.f;
        #pragma unroll
        for (int i = 0; i < DD / 32; i++) s = fmaf(v[lane + i * 32], wc[lane + i * 32], s);
        #pragma unroll
        for (int o = 16; o; o >>= 1) s += __shfl_xor_sync(0xffffffffu, s, o);
        if (!lane) g_cw[ww] = s;
    }
}

// ============ K1: fused sim -> softmax -> c2q (exact fp32) ============
#define K1_SMEM_BYTES (28032 * 4)
__global__ void __launch_bounds__(256) k_attn(
    const float* __restrict__ ctx, const float* __restrict__ question,
    const float* __restrict__ wm)
{
    extern __shared__ float sm[];
    float* Ps    = sm;
    float* Qs2   = sm + 16896;
    float* red   = sm + 25600;
    float* rowm  = sm + 27776;
    float* rowiv = sm + 27904;
    float* Cs    = Ps;
    float* Qs    = Ps + 4224;

    const int b = blockIdx.y, c0 = blockIdx.x << 7;
    const int tid = threadIdx.x, tx = tid & 15, ty = tid >> 4;
    const float* ctxb = ctx + ((size_t)b * CC + c0) * DD;
    const float* qb   = question + (size_t)b * QQ * DD;

    float acc[8][8];
    #pragma unroll
    for (int i = 0; i < 8; i++)
        #pragma unroll
        for (int j = 0; j < 8; j++) acc[i][j] = 0.f;

    for (int dc = 0; dc < DD; dc += 32) {
        #pragma unroll
        for (int i = 0; i < 4; i++) {
            int idx = tid + (i << 8);
            int row = idx >> 3, kk = (idx & 7) << 2;
            float4 v = *(const float4*)(ctxb + (size_t)row * DD + dc + kk);
            Cs[(kk + 0) * 132 + row] = v.x;
            Cs[(kk + 1) * 132 + row] = v.y;
            Cs[(kk + 2) * 132 + row] = v.z;
            Cs[(kk + 3) * 132 + row] = v.w;
            float4 u  = *(const float4*)(qb + (size_t)row * DD + dc + kk);
            float4 w4 = *(const float4*)(wm + dc + kk);
            Qs[(kk + 0) * 132 + row] = u.x * w4.x;
            Qs[(kk + 1) * 132 + row] = u.y * w4.y;
            Qs[(kk + 2) * 132 + row] = u.z * w4.z;
            Qs[(kk + 3) * 132 + row] = u.w * w4.w;
        }
        __syncthreads();
        #pragma unroll 8
        for (int k = 0; k < 32; k++) {
            float4 a0 = *(const float4*)&Cs[k * 132 + (ty << 3)];
            float4 a1 = *(const float4*)&Cs[k * 132 + (ty << 3) + 4];
            float4 b0 = *(const float4*)&Qs[k * 132 + (tx << 3)];
            float4 b1 = *(const float4*)&Qs[k * 132 + (tx << 3) + 4];
            float ar[8] = {a0.x, a0.y, a0.z, a0.w, a1.x, a1.y, a1.z, a1.w};
            float br[8] = {b0.x, b0.y, b0.z, b0.w, b1.x, b1.y, b1.z, b1.w};
            #pragma unroll
            for (int i = 0; i < 8; i++)
                #pragma unroll
                for (int j = 0; j < 8; j++)
                    acc[i][j] = fmaf(ar[i], br[j], acc[i][j]);
        }
        __syncthreads();
    }

    float cb[8], qbv[8];
    #pragma unroll
    for (int i = 0; i < 8; i++) cb[i] = g_cw[b * CC + c0 + (ty << 3) + i];
    #pragma unroll
    for (int j = 0; j < 8; j++) qbv[j] = g_qw[b * QQ + (tx << 3) + j];
    #pragma unroll
    for (int i = 0; i < 8; i++)
        #pragma unroll
        for (int j = 0; j < 8; j++) acc[i][j] += cb[i] + qbv[j];

    #pragma unroll
    for (int i = 0; i < 8; i++) {
        float m = acc[i][0];
        #pragma unroll
        for (int j = 1; j < 8; j++) m = fmaxf(m, acc[i][j]);
        red[((ty << 3) + i) * 17 + tx] = m;
    }
    __syncthreads();
    if (tid < 128) {
        float m = red[tid * 17];
        #pragma unroll
        for (int t = 1; t < 16; t++) m = fmaxf(m, red[tid * 17 + t]);
        rowm[tid] = m;
        g_m[b * CC + c0 + tid] = m;
    }
    __syncthreads();
    #pragma unroll
    for (int i = 0; i < 8; i++) {
        float rm = rowm[(ty << 3) + i];
        float s = 0.f;
        #pragma unroll
        for (int j = 0; j < 8; j++) { acc[i][j] = expf(acc[i][j] - rm); s += acc[i][j]; }
        red[((ty << 3) + i) * 17 + tx] = s;
    }
    __syncthreads();
    if (tid < 128) {
        float s = 0.f;
        #pragma unroll
        for (int t = 0; t < 16; t++) s += red[tid * 17 + t];
        rowiv[tid] = 1.0f / s;
    }
    __syncthreads();
    #pragma unroll
    for (int i = 0; i < 8; i++) {
        float riv = rowiv[(ty << 3) + i];
        #pragma unroll
        for (int j = 0; j < 8; j++)
            Ps[((tx << 3) + j) * 132 + (ty << 3) + i] = acc[i][j] * riv;
    }
    __syncthreads();

    float* outp = g_c2q + ((size_t)b * CC + c0) * DD;
    for (int db = 0; db < DD; db += 64) {
        #pragma unroll
        for (int i = 0; i < 8; i++) {
            int idx = tid + (i << 8);
            int qrow = idx >> 4, c4 = (idx & 15) << 2;
            *(float4*)&Qs2[qrow * 68 + c4] = *(const float4*)(qb + (size_t)qrow * DD + db + c4);
        }
        __syncthreads();
        float o[8][4];
        #pragma unroll
        for (int i = 0; i < 8; i++)
            #pragma unroll
            for (int j = 0; j < 4; j++) o[i][j] = 0.f;
        #pragma unroll 8
        for (int qk = 0; qk < 128; qk++) {
            float4 p0 = *(const float4*)&Ps[qk * 132 + (ty << 3)];
            float4 p1 = *(const float4*)&Ps[qk * 132 + (ty << 3) + 4];
            float4 qv = *(const float4*)&Qs2[qk * 68 + (tx << 2)];
            float pr[8] = {p0.x, p0.y, p0.z, p0.w, p1.x, p1.y, p1.z, p1.w};
            #pragma unroll
            for (int i = 0; i < 8; i++) {
                o[i][0] = fmaf(pr[i], qv.x, o[i][0]);
                o[i][1] = fmaf(pr[i], qv.y, o[i][1]);
                o[i][2] = fmaf(pr[i], qv.z, o[i][2]);
                o[i][3] = fmaf(pr[i], qv.w, o[i][3]);
            }
        }
        #pragma unroll
        for (int i = 0; i < 8; i++)
            *(float4*)&outp[(size_t)((ty << 3) + i) * DD + db + (tx << 2)] =
                make_float4(o[i][0], o[i][1], o[i][2], o[i][3]);
        __syncthreads();
    }
}

// ============ K2: q2c[b,d] = softmax_c(rowmax) . context ============
__global__ void k_q2c(const float* __restrict__ ctx)
{
    __shared__ float w[CC];
    __shared__ float red[256];
    const int b = blockIdx.x, tid = threadIdx.x;
    float lm = -1e30f;
    for (int c = tid; c < CC; c += 256) { float v = g_m[b * CC + c]; w[c] = v; lm = fmaxf(lm, v); }
    red[tid] = lm; __syncthreads();
    for (int s = 128; s > 0; s >>= 1) { if (tid < s) red[tid] = fmaxf(red[tid], red[tid + s]); __syncthreads(); }
    float mx = red[0]; __syncthreads();
    float ls = 0.f;
    for (int c = tid; c < CC; c += 256) { float e = expf(w[c] - mx); w[c] = e; ls += e; }
    red[tid] = ls; __syncthreads();
    for (int s = 128; s > 0; s >>= 1) { if (tid < s) red[tid] += red[tid + s]; __syncthreads(); }
    float inv = 1.0f / red[0]; __syncthreads();
    float accv = 0.f;
    const float* cb = ctx + (size_t)b * CC * DD + tid;
    for (int c = 0; c < CC; c++) accv = fmaf(w[c], cb[(size_t)c * DD], accv);
    g_q2c[b * DD + tid] = accv * inv;
}

// ============ prep: split W into fp16 hi/lo ============
__global__ void k_splitw(const float* __restrict__ W,
                         __half* __restrict__ H, __half* __restrict__ L)
{
    int t = blockIdx.x * 256 + threadIdx.x;
    float4 v = *(const float4*)(W + (size_t)t * 4);
    __half h[4], l[4];
    hsplit(v.x, h[0], l[0]); hsplit(v.y, h[1], l[1]);
    hsplit(v.z, h[2], l[2]); hsplit(v.w, h[3], l[3]);
    *(uint64_t*)(H + (size_t)t * 4) = *(uint64_t*)h;
    *(uint64_t*)(L + (size_t)t * 4) = *(uint64_t*)l;
}

// ============ prep: materialize att as single fp16 ============
__global__ void k_build_att(const float* __restrict__ ctx)
{
    int t = blockIdx.x * 256 + threadIdx.x;
    int r  = t >> 8;
    int c4 = (t & 255) << 2;
    int seg = c4 >> 8, kd = c4 & 255;
    int bb = r >> 10;
    size_t base = (size_t)r * DD + kd;
    float4 av;
    if (seg == 0) {
        av = *(const float4*)(ctx + base);
    } else if (seg == 1) {
        av = *(const float4*)(g_c2q + base);
    } else if (seg == 2) {
        float4 cv = *(const float4*)(ctx + base);
        float4 qv = *(const float4*)(g_c2q + base);
        av = make_float4(cv.x * qv.x, cv.y * qv.y, cv.z * qv.z, cv.w * qv.w);
    } else {
        float4 cv = *(const float4*)(ctx + base);
        float4 qv = *(const float4*)(g_q2c + bb * DD + kd);
        av = make_float4(cv.x * qv.x, cv.y * qv.y, cv.z * qv.z, cv.w * qv.w);
    }
    __half h[4];
    h[0] = __float2half_rn(av.x); h[1] = __float2half_rn(av.y);
    h[2] = __float2half_rn(av.z); h[3] = __float2half_rn(av.w);
    *(uint64_t*)(g_a16 + (size_t)r * FF + c4) = *(uint64_t*)h;
}

// ============ GEMM: fp16x2 (A single, B hi/lo), 128x128 tile ============
// MODE 0: A = g_a16 (att), writes g_h16 = fp16(A@W1^T + b1) masked
// MODE 1: A = g_h16, writes fp32 out = relu((A@W2^T + b2) * mask)
// stage (halfs, SROW=40 padded rows): A[128*40] Bh[128*40] Bl[128*40] = 30720B; x2 stages
#define SROW 40
#define GEMM_SMEM (2 * 3 * 10240)

__device__ __forceinline__ void mma_f16(float* c, const uint32_t* a, uint32_t b0, uint32_t b1) {
    asm volatile(
        "mma.sync.aligned.m16n8k16.row.col.f32.f16.f16.f32 "
        "{%0,%1,%2,%3},{%4,%5,%6,%7},{%8,%9},{%0,%1,%2,%3};"
        : "+f"(c[0]), "+f"(c[1]), "+f"(c[2]), "+f"(c[3])
        : "r"(a[0]), "r"(a[1]), "r"(a[2]), "r"(a[3]), "r"(b0), "r"(b1));
}

template <int MODE>
__global__ void __launch_bounds__(256, 2) k_gemm(
    const __half* __restrict__ A_g,
    const __half* __restrict__ Bh_g, const __half* __restrict__ Bl_g,
    const float* __restrict__ bias, const int* __restrict__ mask,
    float* __restrict__ out)
{
    extern __shared__ uint16_t sm16[];
    const int tid = threadIdx.x, lane = tid & 31, wrp = tid >> 5;
    const int g = lane >> 2, t4 = lane & 3;
    const int wm0 = (wrp >> 1) * 32, wn0 = (wrp & 1) * 64;
    const int m0 = blockIdx.x << 7, n0 = blockIdx.y << 7;
    const int bb = m0 >> 10;

    float acc[2][8][4];
    #pragma unroll
    for (int i = 0; i < 2; i++)
        #pragma unroll
        for (int j = 0; j < 8; j++)
            #pragma unroll
            for (int l = 0; l < 4; l++) acc[i][j][l] = 0.f;

    const uint32_t sbase = (uint32_t)__cvta_generic_to_shared(sm16);

    auto load_stage = [&](int s, int kt) {
        const int k0 = kt << 5;
        const uint32_t sb = sbase + s * 30720;
        #pragma unroll
        for (int j = 0; j < 6; j++) {
            int c = tid + (j << 8);            // 0..1535
            int arr = c >> 9;                  // 0=A 1=Bh 2=Bl
            int mloc = c & 511;
            int row = mloc >> 2, q = mloc & 3;
            uint32_t soff = sb + (uint32_t)arr * 10240u + (uint32_t)(row * SROW + q * 8) * 2;
            const __half* gp;
            if (arr == 0)      gp = A_g  + (size_t)(m0 + row) * FF + k0 + q * 8;
            else if (arr == 1) gp = Bh_g + (size_t)(n0 + row) * FF + k0 + q * 8;
            else               gp = Bl_g + (size_t)(n0 + row) * FF + k0 + q * 8;
            CP16(soff, gp);
        }
        asm volatile("cp.async.commit_group;");
    };

    load_stage(0, 0);

    for (int kt = 0; kt < FF / 32; kt++) {
        const int cur = kt & 1;
        if (kt + 1 < FF / 32) {
            load_stage(cur ^ 1, kt + 1);
            asm volatile("cp.async.wait_group 1;");
        } else {
            asm volatile("cp.async.wait_group 0;");
        }
        __syncthreads();

        const uint16_t* As = sm16 + cur * 15360;
        const uint16_t* Bh = As + 5120;
        const uint16_t* Bl = As + 10240;

        #pragma unroll
        for (int ks = 0; ks < 32; ks += 16) {
            uint32_t a[2][4];
            #pragma unroll
            for (int mt = 0; mt < 2; mt++) {
                int fb = (wm0 + mt * 16 + g) * SROW + ks + 2 * t4;
                a[mt][0] = *(const uint32_t*)&As[fb];
                a[mt][1] = *(const uint32_t*)&As[fb + 8 * SROW];
                a[mt][2] = *(const uint32_t*)&As[fb + 8];
                a[mt][3] = *(const uint32_t*)&As[fb + 8 * SROW + 8];
            }
            #pragma unroll
            for (int nf = 0; nf < 8; nf++) {
                int nb = (wn0 + nf * 8 + g) * SROW + ks + 2 * t4;
                uint32_t bh0 = *(const uint32_t*)&Bh[nb];
                uint32_t bh1 = *(const uint32_t*)&Bh[nb + 8];
                uint32_t bl0 = *(const uint32_t*)&Bl[nb];
                uint32_t bl1 = *(const uint32_t*)&Bl[nb + 8];
                #pragma unroll
                for (int mt = 0; mt < 2; mt++) {
                    mma_f16(acc[mt][nf], a[mt], bh0, bh1);
                    mma_f16(acc[mt][nf], a[mt], bl0, bl1);
                }
            }
        }
        __syncthreads();
    }

    // epilogue
    #pragma unroll
    for (int mt = 0; mt < 2; mt++) {
        int r0 = m0 + wm0 + mt * 16 + g;
        float mv0 = mask[bb * CC + (r0 & 1023)] ? 1.f : 0.f;
        float mv1 = mask[bb * CC + ((r0 + 8) & 1023)] ? 1.f : 0.f;
        #pragma unroll
        for (int nf = 0; nf < 8; nf++) {
            int col = n0 + wn0 + nf * 8 + 2 * t4;
            float bz0 = bias[col], bz1 = bias[col + 1];
            float v00 = (acc[mt][nf][0] + bz0) * mv0;
            float v01 = (acc[mt][nf][1] + bz1) * mv0;
            float v10 = (acc[mt][nf][2] + bz0) * mv1;
            float v11 = (acc[mt][nf][3] + bz1) * mv1;
            size_t o0 = (size_t)r0 * FF + col;
            size_t o1 = (size_t)(r0 + 8) * FF + col;
            if (MODE == 0) {
                __half2 p0 = __floats2half2_rn(v00, v01);
                __half2 p1 = __floats2half2_rn(v10, v11);
                *(__half2*)(g_h16 + o0) = p0;
                *(__half2*)(g_h16 + o1) = p1;
            } else {
                *(float2*)&out[o0] = make_float2(fmaxf(v00, 0.f), fmaxf(v01, 0.f));
                *(float2*)&out[o1] = make_float2(fmaxf(v10, 0.f), fmaxf(v11, 0.f));
            }
        }
    }
}

// =========================== launch ===========================
extern "C" void kernel_launch(void* const* d_in, const int* in_sizes, int n_in,
                              void* d_out, int out_size)
{
    const float* ctx = (const float*)d_in[0];
    const float* qst = (const float*)d_in[1];
    const int*   mask = (const int*)d_in[2];     // bool promoted to int32
    const float* wq = (const float*)d_in[3];
    const float* wc = (const float*)d_in[4];
    const float* wm = (const float*)d_in[5];
    const float* W1 = (const float*)d_in[6];
    const float* b1 = (const float*)d_in[7];
    const float* W2 = (const float*)d_in[8];
    const float* b2 = (const float*)d_in[9];
    float* out = (float*)d_out;

    __half *w1h, *w1l, *w2h, *w2l, *a16, *h16;
    cudaGetSymbolAddress((void**)&w1h, g_w1h);
    cudaGetSymbolAddress((void**)&w1l, g_w1l);
    cudaGetSymbolAddress((void**)&w2h, g_w2h);
    cudaGetSymbolAddress((void**)&w2l, g_w2l);
    cudaGetSymbolAddress((void**)&a16, g_a16);
    cudaGetSymbolAddress((void**)&h16, g_h16);

    cudaFuncSetAttribute(k_attn, cudaFuncAttributeMaxDynamicSharedMemorySize, K1_SMEM_BYTES);
    cudaFuncSetAttribute(k_gemm<0>, cudaFuncAttributeMaxDynamicSharedMemorySize, GEMM_SMEM);
    cudaFuncSetAttribute(k_gemm<1>, cudaFuncAttributeMaxDynamicSharedMemorySize, GEMM_SMEM);

    k_splitw<<<FF * FF / 4 / 256, 256>>>(W1, w1h, w1l);
    k_splitw<<<FF * FF / 4 / 256, 256>>>(W2, w2h, w2l);

    int nwarps = BB * QQ + BB * CC;
    k_dots<<<(nwarps + 7) / 8, 256>>>(qst, ctx, wq, wc);
    k_attn<<<dim3(CC / 128, BB), 256, K1_SMEM_BYTES>>>(ctx, qst, wm);
    k_q2c<<<BB, 256>>>(ctx);
    k_build_att<<<MM, 256>>>(ctx);

    k_gemm<0><<<dim3(MM / 128, FF / 128), 256, GEMM_SMEM>>>(a16, w1h, w1l, b1, mask, nullptr);
    k_gemm<1><<<dim3(MM / 128, FF / 128), 256, GEMM_SMEM>>>(h16, w2h, w2l, b2, mask, out);
}

// round 11
// speedup vs baseline: 3.5675x; 1.4625x over previous
#include <cuda_runtime.h>
#include <cuda_fp16.h>
#include <cstdint>
#include <math.h>

#define BB 32
#define CC 1024
#define QQ 128
#define DD 256
#define FF 1024
#define MM (BB * CC)

// ---- scratch: device globals (no allocations allowed) ----
__device__ float g_c2q[BB * CC * DD];
__device__ float g_m[BB * CC];
__device__ float g_qw[BB * QQ];
__device__ float g_cw[BB * CC];
__device__ float g_q2c[BB * DD];
__device__ __half g_a16[(size_t)MM * FF];     // att, fp16 (64 MB)
__device__ __half g_h16[(size_t)MM * FF];     // h,   fp16 (64 MB)
__device__ __half g_w1[FF * FF];              // W1 fp16
__device__ __half g_w2[FF * FF];              // W2 fp16

#define CP16(smem_b, gptr) \
    asm volatile("cp.async.cg.shared.global [%0], [%1], 16;" :: "r"(smem_b), "l"(gptr))

// ================= K0: qw[b,q]=q.wq ; cw[b,c]=c.wc =================
__global__ void k_dots(const float* __restrict__ q, const float* __restrict__ ctx,
                       const float* __restrict__ wq, const float* __restrict__ wc)
{
    int w = (blockIdx.x * blockDim.x + threadIdx.x) >> 5;
    int lane = threadIdx.x & 31;
    const int NQ = BB * QQ, NC = BB * CC;
    if (w < NQ) {
        const float* v = q + (size_t)w * DD;
        float s = 0.f;
        #pragma unroll
        for (int i = 0; i < DD / 32; i++) s = fmaf(v[lane + i * 32], wq[lane + i * 32], s);
        #pragma unroll
        for (int o = 16; o; o >>= 1) s += __shfl_xor_sync(0xffffffffu, s, o);
        if (!lane) g_qw[w] = s;
    } else if (w < NQ + NC) {
        int ww = w - NQ;
        const float* v = ctx + (size_t)ww * DD;
        float s = 0.f;
        #pragma unroll
        for (int i = 0; i < DD / 32; i++) s = fmaf(v[lane + i * 32], wc[lane + i * 32], s);
        #pragma unroll
        for (int o = 16; o; o >>= 1) s += __shfl_xor_sync(0xffffffffu, s, o);
        if (!lane) g_cw[ww] = s;
    }
}

// ============ K1: fused sim -> softmax -> c2q (exact fp32) ============
#define K1_SMEM_BYTES (28032 * 4)
__global__ void __launch_bounds__(256) k_attn(
    const float* __restrict__ ctx, const float* __restrict__ question,
    const float* __restrict__ wm)
{
    extern __shared__ float sm[];
    float* Ps    = sm;
    float* Qs2   = sm + 16896;
    float* red   = sm + 25600;
    float* rowm  = sm + 27776;
    float* rowiv = sm + 27904;
    float* Cs    = Ps;
    float* Qs    = Ps + 4224;

    const int b = blockIdx.y, c0 = blockIdx.x << 7;
    const int tid = threadIdx.x, tx = tid & 15, ty = tid >> 4;
    const float* ctxb = ctx + ((size_t)b * CC + c0) * DD;
    const float* qb   = question + (size_t)b * QQ * DD;

    float acc[8][8];
    #pragma unroll
    for (int i = 0; i < 8; i++)
        #pragma unroll
        for (int j = 0; j < 8; j++) acc[i][j] = 0.f;

    for (int dc = 0; dc < DD; dc += 32) {
        #pragma unroll
        for (int i = 0; i < 4; i++) {
            int idx = tid + (i << 8);
            int row = idx >> 3, kk = (idx & 7) << 2;
            float4 v = *(const float4*)(ctxb + (size_t)row * DD + dc + kk);
            Cs[(kk + 0) * 132 + row] = v.x;
            Cs[(kk + 1) * 132 + row] = v.y;
            Cs[(kk + 2) * 132 + row] = v.z;
            Cs[(kk + 3) * 132 + row] = v.w;
            float4 u  = *(const float4*)(qb + (size_t)row * DD + dc + kk);
            float4 w4 = *(const float4*)(wm + dc + kk);
            Qs[(kk + 0) * 132 + row] = u.x * w4.x;
            Qs[(kk + 1) * 132 + row] = u.y * w4.y;
            Qs[(kk + 2) * 132 + row] = u.z * w4.z;
            Qs[(kk + 3) * 132 + row] = u.w * w4.w;
        }
        __syncthreads();
        #pragma unroll 8
        for (int k = 0; k < 32; k++) {
            float4 a0 = *(const float4*)&Cs[k * 132 + (ty << 3)];
            float4 a1 = *(const float4*)&Cs[k * 132 + (ty << 3) + 4];
            float4 b0 = *(const float4*)&Qs[k * 132 + (tx << 3)];
            float4 b1 = *(const float4*)&Qs[k * 132 + (tx << 3) + 4];
            float ar[8] = {a0.x, a0.y, a0.z, a0.w, a1.x, a1.y, a1.z, a1.w};
            float br[8] = {b0.x, b0.y, b0.z, b0.w, b1.x, b1.y, b1.z, b1.w};
            #pragma unroll
            for (int i = 0; i < 8; i++)
                #pragma unroll
                for (int j = 0; j < 8; j++)
                    acc[i][j] = fmaf(ar[i], br[j], acc[i][j]);
        }
        __syncthreads();
    }

    float cb[8], qbv[8];
    #pragma unroll
    for (int i = 0; i < 8; i++) cb[i] = g_cw[b * CC + c0 + (ty << 3) + i];
    #pragma unroll
    for (int j = 0; j < 8; j++) qbv[j] = g_qw[b * QQ + (tx << 3) + j];
    #pragma unroll
    for (int i = 0; i < 8; i++)
        #pragma unroll
        for (int j = 0; j < 8; j++) acc[i][j] += cb[i] + qbv[j];

    #pragma unroll
    for (int i = 0; i < 8; i++) {
        float m = acc[i][0];
        #pragma unroll
        for (int j = 1; j < 8; j++) m = fmaxf(m, acc[i][j]);
        red[((ty << 3) + i) * 17 + tx] = m;
    }
    __syncthreads();
    if (tid < 128) {
        float m = red[tid * 17];
        #pragma unroll
        for (int t = 1; t < 16; t++) m = fmaxf(m, red[tid * 17 + t]);
        rowm[tid] = m;
        g_m[b * CC + c0 + tid] = m;
    }
    __syncthreads();
    #pragma unroll
    for (int i = 0; i < 8; i++) {
        float rm = rowm[(ty << 3) + i];
        float s = 0.f;
        #pragma unroll
        for (int j = 0; j < 8; j++) { acc[i][j] = expf(acc[i][j] - rm); s += acc[i][j]; }
        red[((ty << 3) + i) * 17 + tx] = s;
    }
    __syncthreads();
    if (tid < 128) {
        float s = 0.f;
        #pragma unroll
        for (int t = 0; t < 16; t++) s += red[tid * 17 + t];
        rowiv[tid] = 1.0f / s;
    }
    __syncthreads();
    #pragma unroll
    for (int i = 0; i < 8; i++) {
        float riv = rowiv[(ty << 3) + i];
        #pragma unroll
        for (int j = 0; j < 8; j++)
            Ps[((tx << 3) + j) * 132 + (ty << 3) + i] = acc[i][j] * riv;
    }
    __syncthreads();

    float* outp = g_c2q + ((size_t)b * CC + c0) * DD;
    for (int db = 0; db < DD; db += 64) {
        #pragma unroll
        for (int i = 0; i < 8; i++) {
            int idx = tid + (i << 8);
            int qrow = idx >> 4, c4 = (idx & 15) << 2;
            *(float4*)&Qs2[qrow * 68 + c4] = *(const float4*)(qb + (size_t)qrow * DD + db + c4);
        }
        __syncthreads();
        float o[8][4];
        #pragma unroll
        for (int i = 0; i < 8; i++)
            #pragma unroll
            for (int j = 0; j < 4; j++) o[i][j] = 0.f;
        #pragma unroll 8
        for (int qk = 0; qk < 128; qk++) {
            float4 p0 = *(const float4*)&Ps[qk * 132 + (ty << 3)];
            float4 p1 = *(const float4*)&Ps[qk * 132 + (ty << 3) + 4];
            float4 qv = *(const float4*)&Qs2[qk * 68 + (tx << 2)];
            float pr[8] = {p0.x, p0.y, p0.z, p0.w, p1.x, p1.y, p1.z, p1.w};
            #pragma unroll
            for (int i = 0; i < 8; i++) {
                o[i][0] = fmaf(pr[i], qv.x, o[i][0]);
                o[i][1] = fmaf(pr[i], qv.y, o[i][1]);
                o[i][2] = fmaf(pr[i], qv.z, o[i][2]);
                o[i][3] = fmaf(pr[i], qv.w, o[i][3]);
            }
        }
        #pragma unroll
        for (int i = 0; i < 8; i++)
            *(float4*)&outp[(size_t)((ty << 3) + i) * DD + db + (tx << 2)] =
                make_float4(o[i][0], o[i][1], o[i][2], o[i][3]);
        __syncthreads();
    }
}

// ============ K2: q2c[b,d] = softmax_c(rowmax) . context ============
__global__ void k_q2c(const float* __restrict__ ctx)
{
    __shared__ float w[CC];
    __shared__ float red[256];
    const int b = blockIdx.x, tid = threadIdx.x;
    float lm = -1e30f;
    for (int c = tid; c < CC; c += 256) { float v = g_m[b * CC + c]; w[c] = v; lm = fmaxf(lm, v); }
    red[tid] = lm; __syncthreads();
    for (int s = 128; s > 0; s >>= 1) { if (tid < s) red[tid] = fmaxf(red[tid], red[tid + s]); __syncthreads(); }
    float mx = red[0]; __syncthreads();
    float ls = 0.f;
    for (int c = tid; c < CC; c += 256) { float e = expf(w[c] - mx); w[c] = e; ls += e; }
    red[tid] = ls; __syncthreads();
    for (int s = 128; s > 0; s >>= 1) { if (tid < s) red[tid] += red[tid + s]; __syncthreads(); }
    float inv = 1.0f / red[0]; __syncthreads();
    float accv = 0.f;
    const float* cb = ctx + (size_t)b * CC * DD + tid;
    for (int c = 0; c < CC; c++) accv = fmaf(w[c], cb[(size_t)c * DD], accv);
    g_q2c[b * DD + tid] = accv * inv;
}

// ============ prep: convert W to fp16 ============
__global__ void k_cvtw(const float* __restrict__ W, __half* __restrict__ H)
{
    int t = blockIdx.x * 256 + threadIdx.x;
    float4 v = *(const float4*)(W + (size_t)t * 4);
    __half h[4];
    h[0] = __float2half_rn(v.x); h[1] = __float2half_rn(v.y);
    h[2] = __float2half_rn(v.z); h[3] = __float2half_rn(v.w);
    *(uint64_t*)(H + (size_t)t * 4) = *(uint64_t*)h;
}

// ============ prep: materialize att as single fp16 ============
__global__ void k_build_att(const float* __restrict__ ctx)
{
    int t = blockIdx.x * 256 + threadIdx.x;
    int r  = t >> 8;
    int c4 = (t & 255) << 2;
    int seg = c4 >> 8, kd = c4 & 255;
    int bb = r >> 10;
    size_t base = (size_t)r * DD + kd;
    float4 av;
    if (seg == 0) {
        av = *(const float4*)(ctx + base);
    } else if (seg == 1) {
        av = *(const float4*)(g_c2q + base);
    } else if (seg == 2) {
        float4 cv = *(const float4*)(ctx + base);
        float4 qv = *(const float4*)(g_c2q + base);
        av = make_float4(cv.x * qv.x, cv.y * qv.y, cv.z * qv.z, cv.w * qv.w);
    } else {
        float4 cv = *(const float4*)(ctx + base);
        float4 qv = *(const float4*)(g_q2c + bb * DD + kd);
        av = make_float4(cv.x * qv.x, cv.y * qv.y, cv.z * qv.z, cv.w * qv.w);
    }
    __half h[4];
    h[0] = __float2half_rn(av.x); h[1] = __float2half_rn(av.y);
    h[2] = __float2half_rn(av.z); h[3] = __float2half_rn(av.w);
    *(uint64_t*)(g_a16 + (size_t)r * FF + c4) = *(uint64_t*)h;
}

// ============ GEMM: single fp16 x fp16, fp32 acc, 128x128 tile ============
// MODE 0: A = g_a16 (att), writes g_h16 = fp16(A@W1^T + b1) masked
// MODE 1: A = g_h16, writes fp32 out = relu((A@W2^T + b2) * mask)
// stage (halfs, SROW=40 padded rows): A[128*40] B[128*40] = 20480B; x2 stages
#define SROW 40
#define GEMM_SMEM (2 * 2 * 10240)

__device__ __forceinline__ void mma_f16(float* c, const uint32_t* a, uint32_t b0, uint32_t b1) {
    asm volatile(
        "mma.sync.aligned.m16n8k16.row.col.f32.f16.f16.f32 "
        "{%0,%1,%2,%3},{%4,%5,%6,%7},{%8,%9},{%0,%1,%2,%3};"
        : "+f"(c[0]), "+f"(c[1]), "+f"(c[2]), "+f"(c[3])
        : "r"(a[0]), "r"(a[1]), "r"(a[2]), "r"(a[3]), "r"(b0), "r"(b1));
}

template <int MODE>
__global__ void __launch_bounds__(256, 2) k_gemm(
    const __half* __restrict__ A_g, const __half* __restrict__ B_g,
    const float* __restrict__ bias, const int* __restrict__ mask,
    float* __restrict__ out)
{
    extern __shared__ uint16_t sm16[];
    const int tid = threadIdx.x, lane = tid & 31, wrp = tid >> 5;
    const int g = lane >> 2, t4 = lane & 3;
    const int wm0 = (wrp >> 1) * 32, wn0 = (wrp & 1) * 64;
    const int m0 = blockIdx.x << 7, n0 = blockIdx.y << 7;
    const int bb = m0 >> 10;

    float acc[2][8][4];
    #pragma unroll
    for (int i = 0; i < 2; i++)
        #pragma unroll
        for (int j = 0; j < 8; j++)
            #pragma unroll
            for (int l = 0; l < 4; l++) acc[i][j][l] = 0.f;

    const uint32_t sbase = (uint32_t)__cvta_generic_to_shared(sm16);

    auto load_stage = [&](int s, int kt) {
        const int k0 = kt << 5;
        const uint32_t sb = sbase + s * 20480;
        #pragma unroll
        for (int j = 0; j < 4; j++) {
            int c = tid + (j << 8);            // 0..1023
            int arr = c >> 9;                  // 0=A 1=B
            int mloc = c & 511;
            int row = mloc >> 2, q = mloc & 3;
            uint32_t soff = sb + (uint32_t)arr * 10240u + (uint32_t)(row * SROW + q * 8) * 2;
            const __half* gp = (arr == 0)
                ? A_g + (size_t)(m0 + row) * FF + k0 + q * 8
                : B_g + (size_t)(n0 + row) * FF + k0 + q * 8;
            CP16(soff, gp);
        }
        asm volatile("cp.async.commit_group;");
    };

    load_stage(0, 0);

    for (int kt = 0; kt < FF / 32; kt++) {
        const int cur = kt & 1;
        if (kt + 1 < FF / 32) {
            load_stage(cur ^ 1, kt + 1);
            asm volatile("cp.async.wait_group 1;");
        } else {
            asm volatile("cp.async.wait_group 0;");
        }
        __syncthreads();

        const uint16_t* As = sm16 + cur * 10240;
        const uint16_t* Bs = As + 5120;

        #pragma unroll
        for (int ks = 0; ks < 32; ks += 16) {
            uint32_t a[2][4];
            #pragma unroll
            for (int mt = 0; mt < 2; mt++) {
                int fb = (wm0 + mt * 16 + g) * SROW + ks + 2 * t4;
                a[mt][0] = *(const uint32_t*)&As[fb];
                a[mt][1] = *(const uint32_t*)&As[fb + 8 * SROW];
                a[mt][2] = *(const uint32_t*)&As[fb + 8];
                a[mt][3] = *(const uint32_t*)&As[fb + 8 * SROW + 8];
            }
            #pragma unroll
            for (int nf = 0; nf < 8; nf++) {
                int nb = (wn0 + nf * 8 + g) * SROW + ks + 2 * t4;
                uint32_t b0 = *(const uint32_t*)&Bs[nb];
                uint32_t b1 = *(const uint32_t*)&Bs[nb + 8];
                mma_f16(acc[0][nf], a[0], b0, b1);
                mma_f16(acc[1][nf], a[1], b0, b1);
            }
        }
        __syncthreads();
    }

    // epilogue
    #pragma unroll
    for (int mt = 0; mt < 2; mt++) {
        int r0 = m0 + wm0 + mt * 16 + g;
        float mv0 = mask[bb * CC + (r0 & 1023)] ? 1.f : 0.f;
        float mv1 = mask[bb * CC + ((r0 + 8) & 1023)] ? 1.f : 0.f;
        #pragma unroll
        for (int nf = 0; nf < 8; nf++) {
            int col = n0 + wn0 + nf * 8 + 2 * t4;
            float bz0 = bias[col], bz1 = bias[col + 1];
            float v00 = (acc[mt][nf][0] + bz0) * mv0;
            float v01 = (acc[mt][nf][1] + bz1) * mv0;
            float v10 = (acc[mt][nf][2] + bz0) * mv1;
            float v11 = (acc[mt][nf][3] + bz1) * mv1;
            size_t o0 = (size_t)r0 * FF + col;
            size_t o1 = (size_t)(r0 + 8) * FF + col;
            if (MODE == 0) {
                *(__half2*)(g_h16 + o0) = __floats2half2_rn(v00, v01);
                *(__half2*)(g_h16 + o1) = __floats2half2_rn(v10, v11);
            } else {
                *(float2*)&out[o0] = make_float2(fmaxf(v00, 0.f), fmaxf(v01, 0.f));
                *(float2*)&out[o1] = make_float2(fmaxf(v10, 0.f), fmaxf(v11, 0.f));
            }
        }
    }
}

// =========================== launch ===========================
extern "C" void kernel_launch(void* const* d_in, const int* in_sizes, int n_in,
                              void* d_out, int out_size)
{
    const float* ctx = (const float*)d_in[0];
    const float* qst = (const float*)d_in[1];
    const int*   mask = (const int*)d_in[2];     // bool promoted to int32
    const float* wq = (const float*)d_in[3];
    const float* wc = (const float*)d_in[4];
    const float* wm = (const float*)d_in[5];
    const float* W1 = (const float*)d_in[6];
    const float* b1 = (const float*)d_in[7];
    const float* W2 = (const float*)d_in[8];
    const float* b2 = (const float*)d_in[9];
    float* out = (float*)d_out;

    __half *w1, *w2, *a16, *h16;
    cudaGetSymbolAddress((void**)&w1,  g_w1);
    cudaGetSymbolAddress((void**)&w2,  g_w2);
    cudaGetSymbolAddress((void**)&a16, g_a16);
    cudaGetSymbolAddress((void**)&h16, g_h16);

    cudaFuncSetAttribute(k_attn, cudaFuncAttributeMaxDynamicSharedMemorySize, K1_SMEM_BYTES);
    cudaFuncSetAttribute(k_gemm<0>, cudaFuncAttributeMaxDynamicSharedMemorySize, GEMM_SMEM);
    cudaFuncSetAttribute(k_gemm<1>, cudaFuncAttributeMaxDynamicSharedMemorySize, GEMM_SMEM);

    k_cvtw<<<FF * FF / 4 / 256, 256>>>(W1, w1);
    k_cvtw<<<FF * FF / 4 / 256, 256>>>(W2, w2);

    int nwarps = BB * QQ + BB * CC;
    k_dots<<<(nwarps + 7) / 8, 256>>>(qst, ctx, wq, wc);
    k_attn<<<dim3(CC / 128, BB), 256, K1_SMEM_BYTES>>>(ctx, qst, wm);
    k_q2c<<<BB, 256>>>(ctx);
    k_build_att<<<MM, 256>>>(ctx);

    k_gemm<0><<<dim3(MM / 128, FF / 128), 256, GEMM_SMEM>>>(a16, w1, b1, mask, nullptr);
    k_gemm<1><<<dim3(MM / 128, FF / 128), 256, GEMM_SMEM>>>(h16, w2, b2, mask, out);
}